// round 9
// baseline (speedup 1.0000x reference)
#include <cuda_runtime.h>
#include <cstdint>

// x: [8192, 4096] fp32 row-major. loss = N*sum(x*x) - sum_d(colsum_d)^2
#define N_ROWS   8192
#define D_COLS   4096
#define ROW_F4   (D_COLS / 4)               // 1024 float4 per row

// Streaming geometry (R1's k1): 512 blocks, 64-row chunks, 1 float4/thread
#define CBLK     4
#define RCHUNKS  128
#define ROWS_PER_CHUNK (N_ROWS / RCHUNKS)   // 64
#define NBLOCKS  (CBLK * RCHUNKS)           // 512
#define NTHREADS 256

// Fixed-point scales (order-independent integer accumulation -> deterministic)
#define CS_SCALE 17179869184.0f             // 2^34
#define CS_INV   (1.0 / 17179869184.0)
#define SS_SCALE 1073741824.0f              // 2^30
#define SS_INV   (1.0 / 1073741824.0)

// Scratch (__device__ globals, zero-initialized at load; finisher resets them
// after each use so graph replays start clean)
__device__ unsigned long long g_cs_ll[D_COLS];   // 32 KB column-sum accumulator
__device__ unsigned long long g_ss_ll;           // sum-of-squares accumulator
__device__ unsigned           g_cnt;             // arrival counter

// block-reduce float over 256 threads -> valid in thread 0
__device__ __forceinline__ float block_sum_f(float v, float* sh8, int t) {
    #pragma unroll
    for (int o = 16; o > 0; o >>= 1) v += __shfl_down_sync(0xffffffffu, v, o);
    if ((t & 31) == 0) sh8[t >> 5] = v;
    __syncthreads();
    float r = 0.f;
    if (t < 8) {
        r = sh8[t];
        #pragma unroll
        for (int o = 4; o > 0; o >>= 1) r += __shfl_down_sync(0xffu, r, o);
    }
    __syncthreads();
    return r;
}

__global__ __launch_bounds__(NTHREADS, 8)
void stability_loss_kernel(const float* __restrict__ x, float* __restrict__ out)
{
    __shared__ float    sh_red[8];
    __shared__ double   sh_red_d[8];
    __shared__ unsigned sh_old;

    const int t     = threadIdx.x;
    const int cg    = blockIdx.x;            // 0..3
    const int chunk = blockIdx.y;            // 0..127
    const int col   = cg * (NTHREADS * 4) + t * 4;

    // ---------------- Phase 1: stream 1024 cols x 64 rows ----------------
    const float4* __restrict__ p = reinterpret_cast<const float4*>(
        x + (size_t)chunk * ROWS_PER_CHUNK * D_COLS + col);

    float4 cs = make_float4(0.f, 0.f, 0.f, 0.f);
    float  ss = 0.f;

    #pragma unroll 8
    for (int r = 0; r < ROWS_PER_CHUNK; ++r) {
        float4 v = p[(size_t)r * ROW_F4];
        cs.x += v.x; cs.y += v.y; cs.z += v.z; cs.w += v.w;
        ss   += v.x*v.x + v.y*v.y + v.z*v.z + v.w*v.w;
    }

    // ---------------- Deterministic fixed-point accumulation ----------------
    atomicAdd(&g_cs_ll[col + 0], (unsigned long long)llrintf(cs.x * CS_SCALE));
    atomicAdd(&g_cs_ll[col + 1], (unsigned long long)llrintf(cs.y * CS_SCALE));
    atomicAdd(&g_cs_ll[col + 2], (unsigned long long)llrintf(cs.z * CS_SCALE));
    atomicAdd(&g_cs_ll[col + 3], (unsigned long long)llrintf(cs.w * CS_SCALE));

    float tot = block_sum_f(ss, sh_red, t);
    if (t == 0)
        atomicAdd(&g_ss_ll, (unsigned long long)llrintf(tot * SS_SCALE));

    // ---------------- Arrival counter: last block finishes the job ----------------
    __threadfence();
    if (t == 0) sh_old = atomicAdd(&g_cnt, 1u);
    __syncthreads();
    if (sh_old != NBLOCKS - 1) return;

    // ---------------- Finisher: fold 4096 colsums + ss, write out, reset ----------
    {
        double csq = 0.0;
        #pragma unroll
        for (int g = 0; g < 4; ++g) {
            const int c0 = g * 1024 + t * 4;
            #pragma unroll
            for (int j = 0; j < 4; ++j) {
                long long l = (long long)__ldcg(&g_cs_ll[c0 + j]);
                double d = (double)l * CS_INV;
                csq += d * d;
            }
        }
        // block-reduce csq (double)
        #pragma unroll
        for (int o = 16; o > 0; o >>= 1)
            csq += __shfl_down_sync(0xffffffffu, csq, o);
        if ((t & 31) == 0) sh_red_d[t >> 5] = csq;
        __syncthreads();
        if (t < 8) {
            double r = sh_red_d[t];
            #pragma unroll
            for (int o = 4; o > 0; o >>= 1)
                r += __shfl_down_sync(0xffu, r, o);
            if (t == 0) {
                double sstot = (double)(long long)g_ss_ll * SS_INV;
                out[0] = (float)((double)N_ROWS * sstot - r);
            }
        }
        __syncthreads();   // everyone done reading g_cs_ll before reset

        // reset scratch for next graph replay
        #pragma unroll
        for (int g = 0; g < 4; ++g) {
            const int c0 = g * 1024 + t * 4;
            #pragma unroll
            for (int j = 0; j < 4; ++j)
                g_cs_ll[c0 + j] = 0ull;
        }
        if (t == 0) { g_ss_ll = 0ull; g_cnt = 0u; }
    }
}

extern "C" void kernel_launch(void* const* d_in, const int* in_sizes, int n_in,
                              void* d_out, int out_size)
{
    const float* x = (const float*)d_in[0];
    float* out = (float*)d_out;
    (void)in_sizes; (void)n_in; (void)out_size;

    dim3 grid(CBLK, RCHUNKS);
    stability_loss_kernel<<<grid, NTHREADS>>>(x, out);
}

// round 10
// speedup vs baseline: 1.2036x; 1.2036x over previous
#include <cuda_runtime.h>
#include <cstdint>

// x: [8192, 4096] fp32 row-major. loss = N*sum(x*x) - sum_d(colsum_d)^2
#define N_ROWS   8192
#define D_COLS   4096
#define ROW_F4   (D_COLS / 4)               // 1024 float4 per row

#define CBLK     4                          // column groups, 1024 cols (4KB seg/row)
#define RCHUNKS  128                        // row chunks of 64 rows
#define ROWS_PER_CHUNK (N_ROWS / RCHUNKS)   // 64
#define NBLOCKS  (CBLK * RCHUNKS)           // 512
#define NTHREADS 256

#define SEG_BYTES   4096                    // 1024 cols * 4B, contiguous per row
#define STAGE_ROWS  4
#define STAGE_BYTES (STAGE_ROWS * SEG_BYTES)   // 16 KB
#define NSTAGE      3                          // 48 KB dynamic smem
#define NITER       (ROWS_PER_CHUNK / STAGE_ROWS)   // 16

// Deputy-chain tail (proven in R8)
#define SUPER    16
#define NSUPER   (RCHUNKS / SUPER)          // 8

// Scratch (__device__ globals; no allocations allowed)
__device__ float    g_part [RCHUNKS * D_COLS];        // 2 MB level-1 colsum partials
__device__ float    g_part2[CBLK * NSUPER * 1024];    // 128 KB level-2
__device__ float    g_ss_part[NBLOCKS];
__device__ float    g_colsq[CBLK];
__device__ unsigned g_cnt_super[CBLK * NSUPER];
__device__ unsigned g_cnt_cg[CBLK];
__device__ unsigned g_cnt_final;

// ---------------- PTX helpers ----------------
__device__ __forceinline__ uint32_t smem_u32(const void* p) {
    return (uint32_t)__cvta_generic_to_shared(p);
}
__device__ __forceinline__ void mbar_init(uint32_t a, uint32_t cnt) {
    asm volatile("mbarrier.init.shared.b64 [%0], %1;" :: "r"(a), "r"(cnt) : "memory");
}
__device__ __forceinline__ void mbar_expect_tx(uint32_t a, uint32_t bytes) {
    asm volatile("mbarrier.arrive.expect_tx.shared.b64 _, [%0], %1;"
                 :: "r"(a), "r"(bytes) : "memory");
}
__device__ __forceinline__ void bulk_g2s(uint32_t dst, const void* src,
                                         uint32_t bytes, uint32_t mbar) {
    asm volatile("cp.async.bulk.shared::cta.global.mbarrier::complete_tx::bytes "
                 "[%0], [%1], %2, [%3];"
                 :: "r"(dst), "l"(src), "r"(bytes), "r"(mbar) : "memory");
}
__device__ __forceinline__ void mbar_wait(uint32_t mbar, uint32_t parity) {
    asm volatile(
        "{\n\t.reg .pred P;\n\t"
        "W_%=: mbarrier.try_wait.parity.acquire.cta.shared::cta.b64 P, [%0], %1, 0x989680;\n\t"
        "@P bra D_%=;\n\t"
        "bra W_%=;\n\t"
        "D_%=:\n\t}"
        :: "r"(mbar), "r"(parity) : "memory");
}
__device__ __forceinline__ void fence_proxy_async_s() {
    asm volatile("fence.proxy.async.shared::cta;" ::: "memory");
}

// block-reduce one float over 256 threads -> valid in thread 0
__device__ __forceinline__ float block_sum(float v, float* sh8, int t) {
    #pragma unroll
    for (int o = 16; o > 0; o >>= 1) v += __shfl_down_sync(0xffffffffu, v, o);
    if ((t & 31) == 0) sh8[t >> 5] = v;
    __syncthreads();
    float r = 0.f;
    if (t < 8) {
        r = sh8[t];
        #pragma unroll
        for (int o = 4; o > 0; o >>= 1) r += __shfl_down_sync(0xffu, r, o);
    }
    __syncthreads();
    return r;
}

extern __shared__ char smem_dyn[];   // NSTAGE * 16 KB stage buffers

__global__ __launch_bounds__(NTHREADS)
void stability_loss_kernel(const float* __restrict__ x, float* __restrict__ out)
{
    __shared__ alignas(16) uint64_t mb[NSTAGE];
    __shared__ float    sh_red[8];
    __shared__ unsigned sh_old;

    const int t     = threadIdx.x;
    const int cg    = blockIdx.x;            // 0..3
    const int chunk = blockIdx.y;            // 0..127
    const int sg    = chunk >> 4;

    const uint32_t mb0  = smem_u32(&mb[0]);
    const uint32_t stg0 = smem_u32(&smem_dyn[0]);

    // gmem base: rows [chunk*64, +64), cols [cg*1024, +1024)
    const char* gbase = (const char*)x +
        ((size_t)chunk * ROWS_PER_CHUNK * D_COLS + (size_t)cg * 1024) * 4;
    const size_t row_pitch = (size_t)D_COLS * 4;   // 16 KB

    if (t == 0) {
        #pragma unroll
        for (int s = 0; s < NSTAGE; ++s) mbar_init(mb0 + 8 * s, 1);
    }
    __syncthreads();

    // prologue: fill all 3 stages
    if (t == 0) {
        #pragma unroll
        for (int i = 0; i < NSTAGE; ++i) {
            uint32_t mba = mb0 + 8 * i;
            uint32_t dst = stg0 + i * STAGE_BYTES;
            const char* src = gbase + (size_t)i * STAGE_ROWS * row_pitch;
            mbar_expect_tx(mba, STAGE_BYTES);
            #pragma unroll
            for (int j = 0; j < STAGE_ROWS; ++j)
                bulk_g2s(dst + j * SEG_BYTES, src + (size_t)j * row_pitch,
                         SEG_BYTES, mba);
        }
    }

    // ---------------- streaming mainloop ----------------
    float4 cs = make_float4(0.f, 0.f, 0.f, 0.f);
    float  ss = 0.f;

    int slot = 0, phase = 0;
    for (int i = 0; i < NITER; ++i) {
        mbar_wait(mb0 + 8 * slot, phase);

        const float4* sv = reinterpret_cast<const float4*>(
            smem_dyn + slot * STAGE_BYTES);
        #pragma unroll
        for (int r = 0; r < STAGE_ROWS; ++r) {
            float4 v = sv[r * 256 + t];
            cs.x += v.x; cs.y += v.y; cs.z += v.z; cs.w += v.w;
            ss   += v.x*v.x + v.y*v.y + v.z*v.z + v.w*v.w;
        }

        __syncthreads();   // all threads done reading this slot

        if (t == 0 && i + NSTAGE < NITER) {
            const int ni = i + NSTAGE;
            uint32_t mba = mb0 + 8 * slot;
            uint32_t dst = stg0 + slot * STAGE_BYTES;
            const char* src = gbase + (size_t)ni * STAGE_ROWS * row_pitch;
            fence_proxy_async_s();
            mbar_expect_tx(mba, STAGE_BYTES);
            #pragma unroll
            for (int j = 0; j < STAGE_ROWS; ++j)
                bulk_g2s(dst + j * SEG_BYTES, src + (size_t)j * row_pitch,
                         SEG_BYTES, mba);
        }

        if (++slot == NSTAGE) { slot = 0; phase ^= 1; }
    }

    // write colsum partial (thread t owns f4-col cg*256+t of this chunk)
    reinterpret_cast<float4*>(g_part)[(size_t)chunk * ROW_F4 + cg * 256 + t] = cs;

    {
        float tot = block_sum(ss, sh_red, t);
        if (t == 0) g_ss_part[chunk * CBLK + cg] = tot;
    }

    // ---------------- Level 1 -> 2: last arrival of (cg,sg)'s 16 chunks ----------------
    __threadfence();
    if (t == 0) sh_old = atomicAdd(&g_cnt_super[cg * NSUPER + sg], 1u);
    __syncthreads();
    if (sh_old != SUPER - 1) return;
    if (t == 0) g_cnt_super[cg * NSUPER + sg] = 0;   // reset for next replay

    {
        const float4* P = reinterpret_cast<const float4*>(g_part);
        float4 s = make_float4(0.f, 0.f, 0.f, 0.f);
        #pragma unroll 4
        for (int c = 0; c < SUPER; ++c) {
            float4 v = __ldcg(&P[(size_t)(sg * SUPER + c) * ROW_F4 + cg * 256 + t]);
            s.x += v.x; s.y += v.y; s.z += v.z; s.w += v.w;
        }
        reinterpret_cast<float4*>(g_part2)[(size_t)(cg * NSUPER + sg) * 256 + t] = s;
    }

    // ---------------- Level 2 -> colsq: last super-deputy of this cg ----------------
    __threadfence();
    __syncthreads();
    if (t == 0) sh_old = atomicAdd(&g_cnt_cg[cg], 1u);
    __syncthreads();
    if (sh_old != NSUPER - 1) return;
    if (t == 0) g_cnt_cg[cg] = 0;

    {
        const float4* P2 = reinterpret_cast<const float4*>(g_part2);
        float4 s = make_float4(0.f, 0.f, 0.f, 0.f);
        #pragma unroll
        for (int sgi = 0; sgi < NSUPER; ++sgi) {
            float4 v = __ldcg(&P2[(size_t)(cg * NSUPER + sgi) * 256 + t]);
            s.x += v.x; s.y += v.y; s.z += v.z; s.w += v.w;
        }
        float sq = s.x*s.x + s.y*s.y + s.z*s.z + s.w*s.w;
        float csq = block_sum(sq, sh_red, t);
        if (t == 0) g_colsq[cg] = csq;
    }

    // ---------------- Final: last cg-deputy folds everything ----------------
    __threadfence();
    __syncthreads();
    if (t == 0) sh_old = atomicAdd(&g_cnt_final, 1u);
    __syncthreads();
    if (sh_old != CBLK - 1) return;
    if (t == 0) g_cnt_final = 0;

    {
        float ss2 = __ldcg(&g_ss_part[t]) + __ldcg(&g_ss_part[t + 256]);
        float cq  = (t < CBLK) ? __ldcg(&g_colsq[t]) : 0.f;

        #pragma unroll
        for (int o = 16; o > 0; o >>= 1) {
            ss2 += __shfl_down_sync(0xffffffffu, ss2, o);
            cq  += __shfl_down_sync(0xffffffffu, cq,  o);
        }
        __shared__ float sh_a[8], sh_b[8];
        if ((t & 31) == 0) { sh_a[t >> 5] = ss2; sh_b[t >> 5] = cq; }
        __syncthreads();
        if (t < 8) {
            float a = sh_a[t], c2 = sh_b[t];
            #pragma unroll
            for (int o = 4; o > 0; o >>= 1) {
                a  += __shfl_down_sync(0xffu, a,  o);
                c2 += __shfl_down_sync(0xffu, c2, o);
            }
            if (t == 0)
                out[0] = (float)N_ROWS * a - c2;
        }
    }
}

extern "C" void kernel_launch(void* const* d_in, const int* in_sizes, int n_in,
                              void* d_out, int out_size)
{
    const float* x = (const float*)d_in[0];
    float* out = (float*)d_out;
    (void)in_sizes; (void)n_in; (void)out_size;

    cudaFuncSetAttribute(stability_loss_kernel,
                         cudaFuncAttributeMaxDynamicSharedMemorySize,
                         NSTAGE * STAGE_BYTES);

    dim3 grid(CBLK, RCHUNKS);
    stability_loss_kernel<<<grid, NTHREADS, NSTAGE * STAGE_BYTES>>>(x, out);
}

// round 11
// speedup vs baseline: 1.2492x; 1.0379x over previous
#include <cuda_runtime.h>
#include <cstdint>

// x: [8192, 4096] fp32 row-major. loss = N*sum(x*x) - sum_d(colsum_d)^2
#define N_ROWS   8192
#define D_COLS   4096
#define ROW_F4   (D_COLS / 4)               // 1024 float4 per row

#define CBLK     4                          // column groups, 1024 cols (4KB seg/row)
#define RCHUNKS  128                        // row chunks of 64 rows
#define ROWS_PER_CHUNK (N_ROWS / RCHUNKS)   // 64
#define NBLOCKS  (CBLK * RCHUNKS)           // 512
#define NTHREADS 256

#define SEG_BYTES   4096                    // 1024 cols * 4B, contiguous per row
#define STAGE_ROWS  4
#define STAGE_BYTES (STAGE_ROWS * SEG_BYTES)       // 16 KB
#define NSTAGE      3                               // 48 KB dynamic smem
#define NITER       (ROWS_PER_CHUNK / STAGE_ROWS)   // 16

// Deputy-chain tail (proven since R8)
#define SUPER    16
#define NSUPER   (RCHUNKS / SUPER)          // 8

// Scratch (__device__ globals; no allocations allowed)
__device__ float    g_part [RCHUNKS * D_COLS];        // 2 MB level-1 colsum partials
__device__ float    g_part2[CBLK * NSUPER * 1024];    // 128 KB level-2
__device__ float    g_ss_part[NBLOCKS];
__device__ float    g_colsq[CBLK];
__device__ unsigned g_cnt_super[CBLK * NSUPER];
__device__ unsigned g_cnt_cg[CBLK];
__device__ unsigned g_cnt_final;

// ---------------- PTX helpers ----------------
__device__ __forceinline__ uint32_t smem_u32(const void* p) {
    return (uint32_t)__cvta_generic_to_shared(p);
}
__device__ __forceinline__ void mbar_init(uint32_t a, uint32_t cnt) {
    asm volatile("mbarrier.init.shared.b64 [%0], %1;" :: "r"(a), "r"(cnt) : "memory");
}
__device__ __forceinline__ void mbar_arrive(uint32_t a) {
    asm volatile("mbarrier.arrive.shared.b64 _, [%0];" :: "r"(a) : "memory");
}
__device__ __forceinline__ void mbar_expect_tx(uint32_t a, uint32_t bytes) {
    asm volatile("mbarrier.arrive.expect_tx.shared.b64 _, [%0], %1;"
                 :: "r"(a), "r"(bytes) : "memory");
}
__device__ __forceinline__ void bulk_g2s(uint32_t dst, const void* src,
                                         uint32_t bytes, uint32_t mbar) {
    asm volatile("cp.async.bulk.shared::cta.global.mbarrier::complete_tx::bytes "
                 "[%0], [%1], %2, [%3];"
                 :: "r"(dst), "l"(src), "r"(bytes), "r"(mbar) : "memory");
}
__device__ __forceinline__ void mbar_wait(uint32_t mbar, uint32_t parity) {
    asm volatile(
        "{\n\t.reg .pred P;\n\t"
        "W_%=: mbarrier.try_wait.parity.acquire.cta.shared::cta.b64 P, [%0], %1, 0x989680;\n\t"
        "@P bra D_%=;\n\t"
        "bra W_%=;\n\t"
        "D_%=:\n\t}"
        :: "r"(mbar), "r"(parity) : "memory");
}
__device__ __forceinline__ void fence_proxy_async_s() {
    asm volatile("fence.proxy.async.shared::cta;" ::: "memory");
}

// block-reduce one float over 256 threads -> valid in thread 0
__device__ __forceinline__ float block_sum(float v, float* sh8, int t) {
    #pragma unroll
    for (int o = 16; o > 0; o >>= 1) v += __shfl_down_sync(0xffffffffu, v, o);
    if ((t & 31) == 0) sh8[t >> 5] = v;
    __syncthreads();
    float r = 0.f;
    if (t < 8) {
        r = sh8[t];
        #pragma unroll
        for (int o = 4; o > 0; o >>= 1) r += __shfl_down_sync(0xffu, r, o);
    }
    __syncthreads();
    return r;
}

extern __shared__ char smem_dyn[];   // NSTAGE * 16 KB stage buffers

__global__ __launch_bounds__(NTHREADS)
void stability_loss_kernel(const float* __restrict__ x, float* __restrict__ out)
{
    __shared__ alignas(16) uint64_t mb_full[NSTAGE];
    __shared__ alignas(16) uint64_t mb_empty[NSTAGE];
    __shared__ float    sh_red[8];
    __shared__ unsigned sh_old;

    const int t     = threadIdx.x;
    const int cg    = blockIdx.x;            // 0..3
    const int chunk = blockIdx.y;            // 0..127
    const int sg    = chunk >> 4;

    const uint32_t fb0  = smem_u32(&mb_full[0]);
    const uint32_t eb0  = smem_u32(&mb_empty[0]);
    const uint32_t stg0 = smem_u32(&smem_dyn[0]);

    // gmem base: rows [chunk*64, +64), cols [cg*1024, +1024)
    const char* gbase = (const char*)x +
        ((size_t)chunk * ROWS_PER_CHUNK * D_COLS + (size_t)cg * 1024) * 4;
    const size_t row_pitch = (size_t)D_COLS * 4;   // 16 KB

    if (t == 0) {
        #pragma unroll
        for (int s = 0; s < NSTAGE; ++s) {
            mbar_init(fb0 + 8 * s, 1);          // full: one expect_tx producer
            mbar_init(eb0 + 8 * s, NTHREADS);   // empty: all consumers arrive
        }
    }
    __syncthreads();

    // prologue: fill all 3 stages (slots start empty; no empty-wait needed)
    if (t == 0) {
        #pragma unroll
        for (int i = 0; i < NSTAGE; ++i) {
            uint32_t mba = fb0 + 8 * i;
            uint32_t dst = stg0 + i * STAGE_BYTES;
            const char* src = gbase + (size_t)i * STAGE_ROWS * row_pitch;
            mbar_expect_tx(mba, STAGE_BYTES);
            #pragma unroll
            for (int j = 0; j < STAGE_ROWS; ++j)
                bulk_g2s(dst + j * SEG_BYTES, src + (size_t)j * row_pitch,
                         SEG_BYTES, mba);
        }
    }

    // ---------------- streaming mainloop (producer-consumer ring) ----------------
    float4 cs = make_float4(0.f, 0.f, 0.f, 0.f);
    float  ss = 0.f;

    int slot = 0, fphase = 0, ephase = 0;
    for (int i = 0; i < NITER; ++i) {
        mbar_wait(fb0 + 8 * slot, fphase);

        const float4* sv = reinterpret_cast<const float4*>(
            smem_dyn + slot * STAGE_BYTES);
        #pragma unroll
        for (int r = 0; r < STAGE_ROWS; ++r) {
            float4 v = sv[r * 256 + t];
            cs.x += v.x; cs.y += v.y; cs.z += v.z; cs.w += v.w;
            ss   += v.x*v.x + v.y*v.y + v.z*v.z + v.w*v.w;
        }

        // signal this slot consumed; other warps run ahead immediately
        mbar_arrive(eb0 + 8 * slot);

        if (t == 0 && i + NSTAGE < NITER) {
            // wait until ALL threads have consumed this slot, then refill it
            mbar_wait(eb0 + 8 * slot, ephase);
            const int ni = i + NSTAGE;
            uint32_t mba = fb0 + 8 * slot;
            uint32_t dst = stg0 + slot * STAGE_BYTES;
            const char* src = gbase + (size_t)ni * STAGE_ROWS * row_pitch;
            fence_proxy_async_s();
            mbar_expect_tx(mba, STAGE_BYTES);
            #pragma unroll
            for (int j = 0; j < STAGE_ROWS; ++j)
                bulk_g2s(dst + j * SEG_BYTES, src + (size_t)j * row_pitch,
                         SEG_BYTES, mba);
        }

        if (++slot == NSTAGE) { slot = 0; fphase ^= 1; ephase ^= 1; }
    }
    __syncthreads();   // re-converge before tail

    // write colsum partial (thread t owns f4-col cg*256+t of this chunk)
    reinterpret_cast<float4*>(g_part)[(size_t)chunk * ROW_F4 + cg * 256 + t] = cs;

    {
        float tot = block_sum(ss, sh_red, t);
        if (t == 0) g_ss_part[chunk * CBLK + cg] = tot;
    }

    // ---------------- Level 1 -> 2: last arrival of (cg,sg)'s 16 chunks ----------------
    __threadfence();
    if (t == 0) sh_old = atomicAdd(&g_cnt_super[cg * NSUPER + sg], 1u);
    __syncthreads();
    if (sh_old != SUPER - 1) return;
    if (t == 0) g_cnt_super[cg * NSUPER + sg] = 0;   // reset for next replay

    {
        const float4* P = reinterpret_cast<const float4*>(g_part);
        float4 s = make_float4(0.f, 0.f, 0.f, 0.f);
        #pragma unroll 4
        for (int c = 0; c < SUPER; ++c) {
            float4 v = __ldcg(&P[(size_t)(sg * SUPER + c) * ROW_F4 + cg * 256 + t]);
            s.x += v.x; s.y += v.y; s.z += v.z; s.w += v.w;
        }
        reinterpret_cast<float4*>(g_part2)[(size_t)(cg * NSUPER + sg) * 256 + t] = s;
    }

    // ---------------- Level 2 -> colsq: last super-deputy of this cg ----------------
    __threadfence();
    __syncthreads();
    if (t == 0) sh_old = atomicAdd(&g_cnt_cg[cg], 1u);
    __syncthreads();
    if (sh_old != NSUPER - 1) return;
    if (t == 0) g_cnt_cg[cg] = 0;

    {
        const float4* P2 = reinterpret_cast<const float4*>(g_part2);
        float4 s = make_float4(0.f, 0.f, 0.f, 0.f);
        #pragma unroll
        for (int sgi = 0; sgi < NSUPER; ++sgi) {
            float4 v = __ldcg(&P2[(size_t)(cg * NSUPER + sgi) * 256 + t]);
            s.x += v.x; s.y += v.y; s.z += v.z; s.w += v.w;
        }
        float sq = s.x*s.x + s.y*s.y + s.z*s.z + s.w*s.w;
        float csq = block_sum(sq, sh_red, t);
        if (t == 0) g_colsq[cg] = csq;
    }

    // ---------------- Final: last cg-deputy folds everything ----------------
    __threadfence();
    __syncthreads();
    if (t == 0) sh_old = atomicAdd(&g_cnt_final, 1u);
    __syncthreads();
    if (sh_old != CBLK - 1) return;
    if (t == 0) g_cnt_final = 0;

    {
        float ss2 = __ldcg(&g_ss_part[t]) + __ldcg(&g_ss_part[t + 256]);
        float cq  = (t < CBLK) ? __ldcg(&g_colsq[t]) : 0.f;

        #pragma unroll
        for (int o = 16; o > 0; o >>= 1) {
            ss2 += __shfl_down_sync(0xffffffffu, ss2, o);
            cq  += __shfl_down_sync(0xffffffffu, cq,  o);
        }
        __shared__ float sh_a[8], sh_b[8];
        if ((t & 31) == 0) { sh_a[t >> 5] = ss2; sh_b[t >> 5] = cq; }
        __syncthreads();
        if (t < 8) {
            float a = sh_a[t], c2 = sh_b[t];
            #pragma unroll
            for (int o = 4; o > 0; o >>= 1) {
                a  += __shfl_down_sync(0xffu, a,  o);
                c2 += __shfl_down_sync(0xffu, c2, o);
            }
            if (t == 0)
                out[0] = (float)N_ROWS * a - c2;
        }
    }
}

extern "C" void kernel_launch(void* const* d_in, const int* in_sizes, int n_in,
                              void* d_out, int out_size)
{
    const float* x = (const float*)d_in[0];
    float* out = (float*)d_out;
    (void)in_sizes; (void)n_in; (void)out_size;

    cudaFuncSetAttribute(stability_loss_kernel,
                         cudaFuncAttributeMaxDynamicSharedMemorySize,
                         NSTAGE * STAGE_BYTES);

    dim3 grid(CBLK, RCHUNKS);
    stability_loss_kernel<<<grid, NTHREADS, NSTAGE * STAGE_BYTES>>>(x, out);
}